// round 15
// baseline (speedup 1.0000x reference)
#include <cuda_runtime.h>
#include <cstdint>

// Problem constants
#define B_  8
#define S_  1024
#define C_  768
#define H_  12
#define D_  64
#define BS_ (B_ * S_)            // 8192
#define BHSD (B_ * H_ * S_ * D_) // 6291456

// Scratch (allocation-free: static device globals)
__device__ float g_q[BHSD];      // tf32 bits, pre-scaled by QSCALE
__device__ float g_k[BHSD];      // tf32 bits
__device__ float g_v[BHSD];      // tf32 bits
__device__ float g_y[BS_ * C_];  // tf32 bits
// tf32-preconverted operands (bits stored as float)
__device__ float g_xc[BS_ * C_];
__device__ float g_wqc[3 * C_ * C_];
__device__ float g_woc[C_ * C_];

#define QSCALE 0.18033688011f    // 0.125 * log2(e)

// ---------------------------------------------------------------------------
// helpers
// ---------------------------------------------------------------------------
__device__ __forceinline__ uint32_t f2tf32(float f) {
    uint32_t r;
    asm("cvt.rna.tf32.f32 %0, %1;" : "=r"(r) : "f"(f));
    return r;
}
__device__ __forceinline__ float fexp2(float x) {
    float y;
    asm("ex2.approx.f32 %0, %1;" : "=f"(y) : "f"(x));
    return y;
}
__device__ __forceinline__ void mma_tf32(float* c, const uint32_t* a,
                                         const uint32_t* b) {
    asm volatile(
        "mma.sync.aligned.m16n8k8.row.col.f32.tf32.tf32.f32 "
        "{%0,%1,%2,%3}, {%4,%5,%6,%7}, {%8,%9}, {%0,%1,%2,%3};"
        : "+f"(c[0]), "+f"(c[1]), "+f"(c[2]), "+f"(c[3])
        : "r"(a[0]), "r"(a[1]), "r"(a[2]), "r"(a[3]), "r"(b[0]), "r"(b[1]));
}
__device__ __forceinline__ uint32_t smem_u32(const void* p) {
    uint32_t a;
    asm("{ .reg .u64 t; cvta.to.shared.u64 t, %1; cvt.u32.u64 %0, t; }"
        : "=r"(a) : "l"(p));
    return a;
}
__device__ __forceinline__ void cp16(uint32_t saddr, const void* g) {
    asm volatile("cp.async.cg.shared.global [%0], [%1], 16;"
                 :: "r"(saddr), "l"(g) : "memory");
}
#define CP_COMMIT() asm volatile("cp.async.commit_group;" ::: "memory")
#define CP_WAIT1()  asm volatile("cp.async.wait_group 1;" ::: "memory")

// ===========================================================================
// Prep: convert x, w_qkv, w_out to tf32 bit patterns (stored as float)
// ===========================================================================
__global__ void prep_convert(const float* __restrict__ x,
                             const float* __restrict__ wq,
                             const float* __restrict__ wo)
{
    const int stride = gridDim.x * blockDim.x;
    const int i0 = blockIdx.x * blockDim.x + threadIdx.x;
    for (int j = i0; j < BS_ * C_ / 4; j += stride) {
        float4 v = ((const float4*)x)[j];
        ((uint4*)g_xc)[j] = make_uint4(f2tf32(v.x), f2tf32(v.y),
                                       f2tf32(v.z), f2tf32(v.w));
    }
    for (int j = i0; j < 3 * C_ * C_ / 4; j += stride) {
        float4 v = ((const float4*)wq)[j];
        ((uint4*)g_wqc)[j] = make_uint4(f2tf32(v.x), f2tf32(v.y),
                                        f2tf32(v.z), f2tf32(v.w));
    }
    for (int j = i0; j < C_ * C_ / 4; j += stride) {
        float4 v = ((const float4*)wo)[j];
        ((uint4*)g_woc)[j] = make_uint4(f2tf32(v.x), f2tf32(v.y),
                                        f2tf32(v.z), f2tf32(v.w));
    }
}

// ===========================================================================
// Tensor-core GEMM NT with cp.async double-buffered staging (unchanged R14).
// MODE 0 epilogue emits tf32 bits (q pre-scaled by QSCALE).
// ===========================================================================
#define STW (128 * 36)
#define GEMM_SMEM_BYTES (4 * STW * 4)  // 73728
#define NKC (C_ / 32)                  // 24

template <int MODE>
__global__ __launch_bounds__(256) void mmagemm(
    const float* __restrict__ bias, float* __restrict__ Cout)
{
    extern __shared__ uint32_t sg[];
    const uint32_t sbase = smem_u32(sg);

    const float* A = (MODE == 1) ? (const float*)g_y : (const float*)g_xc;
    const float* Bm = (MODE == 1) ? (const float*)g_woc : (const float*)g_wqc;

    const int tid  = threadIdx.x;
    const int wid  = tid >> 5;
    const int lane = tid & 31;
    const int g = lane >> 2;
    const int t = lane & 3;
    const int wr = (wid >> 2) * 64;
    const int wc = (wid & 3) * 32;
    const int bm = blockIdx.y * 128;
    const int bn = blockIdx.x * 128;

    int soff[4];
    const float *Ap[4], *Bp[4];
    #pragma unroll
    for (int i = 0; i < 4; i++) {
        const int idx = tid + i * 256;
        const int row = idx >> 3;
        const int f4  = (idx & 7) << 2;
        soff[i] = (row * 36 + f4) * 4;
        Ap[i] = A  + (size_t)(bm + row) * C_ + f4;
        Bp[i] = Bm + (size_t)(bn + row) * C_ + f4;
    }

    float acc[4][4][4];
    #pragma unroll
    for (int i = 0; i < 4; i++)
        #pragma unroll
        for (int j = 0; j < 4; j++)
            #pragma unroll
            for (int r = 0; r < 4; r++) acc[i][j][r] = 0.f;

    auto issue = [&](int c) {
        if (c < NKC) {
            const uint32_t ab = sbase + (uint32_t)(c & 1) * (2 * STW * 4);
            const uint32_t bb = ab + STW * 4;
            const int k0 = c * 32;
            #pragma unroll
            for (int i = 0; i < 4; i++) {
                cp16(ab + soff[i], Ap[i] + k0);
                cp16(bb + soff[i], Bp[i] + k0);
            }
        }
        CP_COMMIT();
    };

    issue(0);
    for (int kc = 0; kc < NKC; kc++) {
        issue(kc + 1);
        CP_WAIT1();
        __syncthreads();

        const uint32_t* As = sg + (kc & 1) * (2 * STW);
        const uint32_t* Bs = As + STW;
        #pragma unroll
        for (int ks = 0; ks < 4; ks++) {
            const int kk = ks * 8;
            uint32_t af[4][4], bf[4][2];
            #pragma unroll
            for (int mt = 0; mt < 4; mt++) {
                const int r = wr + mt * 16 + g;
                af[mt][0] = As[r * 36 + kk + t];
                af[mt][1] = As[(r + 8) * 36 + kk + t];
                af[mt][2] = As[r * 36 + kk + t + 4];
                af[mt][3] = As[(r + 8) * 36 + kk + t + 4];
            }
            #pragma unroll
            for (int nt = 0; nt < 4; nt++) {
                const int n = wc + nt * 8 + g;
                bf[nt][0] = Bs[n * 36 + kk + t];
                bf[nt][1] = Bs[n * 36 + kk + t + 4];
            }
            #pragma unroll
            for (int mt = 0; mt < 4; mt++)
                #pragma unroll
                for (int nt = 0; nt < 4; nt++)
                    mma_tf32(acc[mt][nt], af[mt], bf[nt]);
        }
        __syncthreads();
    }

    #pragma unroll
    for (int mt = 0; mt < 4; mt++) {
        #pragma unroll
        for (int nt = 0; nt < 4; nt++) {
            const int col = wc + nt * 8 + 2 * t;
            const int r0  = bm + wr + mt * 16 + g;
            const int r1  = r0 + 8;
            const float bv0 = bias[bn + col];
            const float bv1 = bias[bn + col + 1];
            if (MODE == 0) {
                const int comp = bn / C_;
                float* db = (comp == 0) ? g_q : (comp == 1) ? g_k : g_v;
                const float sc = (comp == 0) ? QSCALE : 1.0f;
                float2 lo = make_float2(
                    __uint_as_float(f2tf32((acc[mt][nt][0] + bv0) * sc)),
                    __uint_as_float(f2tf32((acc[mt][nt][1] + bv1) * sc)));
                float2 hi = make_float2(
                    __uint_as_float(f2tf32((acc[mt][nt][2] + bv0) * sc)),
                    __uint_as_float(f2tf32((acc[mt][nt][3] + bv1) * sc)));
                const int c = bn - comp * C_ + col;
                const int h = c >> 6, d = c & 63;
                {
                    const int b = r0 >> 10, s = r0 & 1023;
                    *(float2*)(db + (size_t)(b * H_ + h) * (S_ * D_) +
                               (size_t)s * D_ + d) = lo;
                }
                {
                    const int b = r1 >> 10, s = r1 & 1023;
                    *(float2*)(db + (size_t)(b * H_ + h) * (S_ * D_) +
                               (size_t)s * D_ + d) = hi;
                }
            } else {
                *(float2*)(Cout + (size_t)r0 * C_ + bn + col) =
                    make_float2(acc[mt][nt][0] + bv0, acc[mt][nt][1] + bv1);
                *(float2*)(Cout + (size_t)r1 * C_ + bn + col) =
                    make_float2(acc[mt][nt][2] + bv0, acc[mt][nt][3] + bv1);
            }
        }
    }
}

// ===========================================================================
// Flash attention, KEY TILE = 64 (halved barrier/softmax-pass count).
// Raw LDG staging (operands already tf32 bits). mma QK^T -> S spill ->
// in-place SIMT softmax (32 cols/thread) -> mma P@V.
// grid (8, 96), 256 threads, 8 warps x 16 query rows.
// smem words: sQ 128x68, sK 64x68, sV 64x72, sSP 128x68, sFac/sL 128 each.
// ===========================================================================
#define AT_SQ   0
#define AT_SK   (128 * 68)                      // 8704
#define AT_SV   (AT_SK + 64 * 68)               // 13056
#define AT_SS   (AT_SV + 64 * 72)               // 17664
#define AT_SFAC (AT_SS + 128 * 68)              // 26368
#define AT_SL   (AT_SFAC + 128)                 // 26496
#define AT_SMEM_WORDS (AT_SL + 128)             // 26624
#define AT_SMEM_BYTES (AT_SMEM_WORDS * 4)       // 106496

__global__ __launch_bounds__(256) void attn_mma(const int* __restrict__ mask)
{
    extern __shared__ uint32_t su[];
    uint32_t (*sQ)[68]  = (uint32_t(*)[68])(su + AT_SQ);
    uint32_t (*sK)[68]  = (uint32_t(*)[68])(su + AT_SK);
    uint32_t (*sV)[72]  = (uint32_t(*)[72])(su + AT_SV);
    float    (*sSP)[68] = (float(*)[68])(su + AT_SS);
    float* sFac = (float*)(su + AT_SFAC);
    float* sL   = (float*)(su + AT_SL);

    const int tid  = threadIdx.x;
    const int wid  = tid >> 5;
    const int lane = tid & 31;
    const int g = lane >> 2;
    const int t = lane & 3;
    const int m0 = wid * 16;

    const int it  = (int)gridDim.x - 1 - (int)blockIdx.x;  // heavy tiles first
    const int bh  = blockIdx.y;
    const int b   = bh / H_;
    const int h   = bh - b * H_;
    const int row0 = it * 128;

    const float* Q  = g_q + (size_t)bh * (S_ * D_) + (size_t)row0 * D_;
    const float* K0 = g_k + (size_t)bh * (S_ * D_);
    const float* V0 = g_v + (size_t)bh * (S_ * D_);
    const int* maskp = mask + b * S_;

    // Stage Q raw (already QSCALE-scaled tf32 bits): 128 x 64
    #pragma unroll
    for (int i = 0; i < 8; i++) {
        const int idx = tid + i * 256;
        const int r = idx >> 4, c4 = (idx & 15) << 2;
        *(float4*)&sQ[r][c4] = *(const float4*)(Q + r * D_ + c4);
    }

    // Softmax ownership: thread tid owns row tid>>1, cols (tid&1)*32..+31
    const int srow  = tid >> 1;
    const int scol0 = (tid & 1) << 5;
    const int growo = row0 + srow;
    float m_row = -1e30f, l_row = 0.f;

    float o[8][4];
    #pragma unroll
    for (int nv = 0; nv < 8; nv++)
        #pragma unroll
        for (int r = 0; r < 4; r++) o[nv][r] = 0.f;

    const int ntiles = 2 * it + 2;
    for (int jt = 0; jt < ntiles; jt++) {
        const int kb = jt * 64;
        __syncthreads();    // prev P@V done reading sSP/sV
        // Stage K and V tiles (64 rows x 64 dims each), raw tf32 bits
        #pragma unroll
        for (int i = 0; i < 4; i++) {
            const int idx = tid + i * 256;      // 0..1023
            const int r = idx >> 4, c4 = (idx & 15) << 2;
            *(float4*)&sK[r][c4] =
                *(const float4*)(K0 + (size_t)(kb + r) * D_ + c4);
            *(float4*)&sV[r][c4] =
                *(const float4*)(V0 + (size_t)(kb + r) * D_ + c4);
        }
        __syncthreads();

        // S = Q K^T : warp tile 16x64 (nt=8), 8 k-steps [validated pattern]
        float sacc[8][4];
        #pragma unroll
        for (int nt = 0; nt < 8; nt++)
            #pragma unroll
            for (int r = 0; r < 4; r++) sacc[nt][r] = 0.f;

        #pragma unroll
        for (int ks = 0; ks < 8; ks++) {
            const int kc = ks * 8;
            uint32_t af[4];
            af[0] = sQ[m0 + g][kc + t];
            af[1] = sQ[m0 + g + 8][kc + t];
            af[2] = sQ[m0 + g][kc + t + 4];
            af[3] = sQ[m0 + g + 8][kc + t + 4];
            #pragma unroll
            for (int nt = 0; nt < 8; nt++) {
                uint32_t bf[2];
                bf[0] = sK[nt * 8 + g][kc + t];
                bf[1] = sK[nt * 8 + g][kc + t + 4];
                mma_tf32(sacc[nt], af, bf);
            }
        }

        // Spill S fragments (validated C-layout; 68 stride ≡ 36 mod 32)
        #pragma unroll
        for (int nt = 0; nt < 8; nt++) {
            const int col = nt * 8 + 2 * t;
            *(float2*)&sSP[m0 + g][col] =
                make_float2(sacc[nt][0], sacc[nt][1]);
            *(float2*)&sSP[m0 + g + 8][col] =
                make_float2(sacc[nt][2], sacc[nt][3]);
        }
        __syncthreads();

        // SIMT softmax, in place; 32 cols per thread
        {
            float sv[32];
            #pragma unroll
            for (int j4 = 0; j4 < 8; j4++) {
                int4 km = *(const int4*)(maskp + kb + scol0 + j4 * 4);
                const int base = scol0 + j4 * 4;
                const int cg = kb + base;
                sv[j4*4+0] = ((cg+0) <= growo && km.x) ? sSP[srow][base+0] : -1e30f;
                sv[j4*4+1] = ((cg+1) <= growo && km.y) ? sSP[srow][base+1] : -1e30f;
                sv[j4*4+2] = ((cg+2) <= growo && km.z) ? sSP[srow][base+2] : -1e30f;
                sv[j4*4+3] = ((cg+3) <= growo && km.w) ? sSP[srow][base+3] : -1e30f;
            }
            float lm = sv[0];
            #pragma unroll
            for (int j = 1; j < 32; j++) lm = fmaxf(lm, sv[j]);
            lm = fmaxf(lm, __shfl_xor_sync(0xffffffffu, lm, 1));
            const float mnew = fmaxf(fmaxf(m_row, lm), -50.0f);
            const float fac = fexp2(m_row - mnew);
            float rs = 0.f;
            #pragma unroll
            for (int j = 0; j < 32; j++) {
                const float p = fexp2(sv[j] - mnew);
                rs += p;
                sSP[srow][scol0 + j] = p;
            }
            rs += __shfl_xor_sync(0xffffffffu, rs, 1);
            l_row = l_row * fac + rs;
            m_row = mnew;
            if ((tid & 1) == 0) sFac[srow] = fac;
        }
        __syncthreads();

        // Rescale O, then O += P @ V (A = sP 16x64, B = sV 64x64)
        const float f0 = sFac[m0 + g];
        const float f1 = sFac[m0 + g + 8];
        #pragma unroll
        for (int nv = 0; nv < 8; nv++) {
            o[nv][0] *= f0; o[nv][1] *= f0;
            o[nv][2] *= f1; o[nv][3] *= f1;
        }
        #pragma unroll
        for (int ks = 0; ks < 8; ks++) {
            const int kc = ks * 8;
            uint32_t af[4];
            af[0] = __float_as_uint(sSP[m0 + g][kc + t]);
            af[1] = __float_as_uint(sSP[m0 + g + 8][kc + t]);
            af[2] = __float_as_uint(sSP[m0 + g][kc + t + 4]);
            af[3] = __float_as_uint(sSP[m0 + g + 8][kc + t + 4]);
            #pragma unroll
            for (int nv = 0; nv < 8; nv++) {
                uint32_t bf[2];
                bf[0] = sV[kc + t][nv * 8 + g];
                bf[1] = sV[kc + t + 4][nv * 8 + g];
                mma_tf32(o[nv], af, bf);
            }
        }
    }

    if ((tid & 1) == 0) sL[srow] = l_row;
    __syncthreads();

    const int gr0 = row0 + m0 + g;
    const int gr1 = gr0 + 8;
    const float lv0 = sL[m0 + g];
    const float lv1 = sL[m0 + g + 8];
    const float inv0 = (lv0 > 0.f) ? (1.f / lv0) : 0.f;
    const float inv1 = (lv1 > 0.f) ? (1.f / lv1) : 0.f;
    float* y0 = g_y + (size_t)(b * S_ + gr0) * C_ + h * D_;
    float* y1 = g_y + (size_t)(b * S_ + gr1) * C_ + h * D_;
    #pragma unroll
    for (int nv = 0; nv < 8; nv++) {
        const int col = nv * 8 + 2 * t;
        *(float2*)(y0 + col) = make_float2(
            __uint_as_float(f2tf32(o[nv][0] * inv0)),
            __uint_as_float(f2tf32(o[nv][1] * inv0)));
        *(float2*)(y1 + col) = make_float2(
            __uint_as_float(f2tf32(o[nv][2] * inv1)),
            __uint_as_float(f2tf32(o[nv][3] * inv1)));
    }
}

// ---------------------------------------------------------------------------
extern "C" void kernel_launch(void* const* d_in, const int* in_sizes, int n_in,
                              void* d_out, int out_size)
{
    const float* x      = (const float*)d_in[0];
    const float* w_qkv  = (const float*)d_in[1];
    const float* b_qkv  = (const float*)d_in[2];
    const float* w_out  = (const float*)d_in[3];
    const float* b_out  = (const float*)d_in[4];
    const int*   amask  = (const int*)d_in[5];
    float* out = (float*)d_out;

    cudaFuncSetAttribute(mmagemm<0>,
                         cudaFuncAttributeMaxDynamicSharedMemorySize,
                         GEMM_SMEM_BYTES);
    cudaFuncSetAttribute(mmagemm<1>,
                         cudaFuncAttributeMaxDynamicSharedMemorySize,
                         GEMM_SMEM_BYTES);
    cudaFuncSetAttribute(attn_mma,
                         cudaFuncAttributeMaxDynamicSharedMemorySize,
                         AT_SMEM_BYTES);

    // 0) Pre-convert operands to tf32 bit patterns
    prep_convert<<<592, 256>>>(x, w_qkv, w_out);
    // 1) QKV projection -> g_q (scaled tf32) / g_k / g_v (tf32)
    {
        dim3 grid((3 * C_) / 128, BS_ / 128);   // (18, 64)
        mmagemm<0><<<grid, 256, GEMM_SMEM_BYTES>>>(b_qkv, nullptr);
    }
    // 2) Flash attention (64-key tiles) -> g_y (tf32)
    {
        dim3 grid(S_ / 128, B_ * H_);           // (8, 96)
        attn_mma<<<grid, 256, AT_SMEM_BYTES>>>(amask);
    }
    // 3) Output projection -> d_out
    {
        dim3 grid(C_ / 128, BS_ / 128);         // (6, 64)
        mmagemm<1><<<grid, 256, GEMM_SMEM_BYTES>>>(b_out, out);
    }
}

// round 16
// speedup vs baseline: 1.2979x; 1.2979x over previous
#include <cuda_runtime.h>
#include <cuda_fp16.h>
#include <cstdint>

// Problem constants
#define B_  8
#define S_  1024
#define C_  768
#define H_  12
#define D_  64
#define BS_ (B_ * S_)            // 8192
#define BHSD (B_ * H_ * S_ * D_) // 6291456

// Scratch (allocation-free: static device globals)
__device__ float  g_q[BHSD];       // tf32 bits, pre-scaled by QSCALE
__device__ float  g_k[BHSD];       // tf32 bits
__device__ float  g_v[BHSD];       // tf32 bits
__device__ __half g_yh[BS_ * C_];  // attention output, fp16
// fp16-preconverted GEMM operands
__device__ __half g_xh[BS_ * C_];
__device__ __half g_wqh[3 * C_ * C_];
__device__ __half g_woh[C_ * C_];

#define QSCALE 0.18033688011f    // 0.125 * log2(e)

// ---------------------------------------------------------------------------
// helpers
// ---------------------------------------------------------------------------
__device__ __forceinline__ uint32_t f2tf32(float f) {
    uint32_t r;
    asm("cvt.rna.tf32.f32 %0, %1;" : "=r"(r) : "f"(f));
    return r;
}
__device__ __forceinline__ float fexp2(float x) {
    float y;
    asm("ex2.approx.f32 %0, %1;" : "=f"(y) : "f"(x));
    return y;
}
__device__ __forceinline__ void mma_tf32(float* c, const uint32_t* a,
                                         const uint32_t* b) {
    asm volatile(
        "mma.sync.aligned.m16n8k8.row.col.f32.tf32.tf32.f32 "
        "{%0,%1,%2,%3}, {%4,%5,%6,%7}, {%8,%9}, {%0,%1,%2,%3};"
        : "+f"(c[0]), "+f"(c[1]), "+f"(c[2]), "+f"(c[3])
        : "r"(a[0]), "r"(a[1]), "r"(a[2]), "r"(a[3]), "r"(b[0]), "r"(b[1]));
}
__device__ __forceinline__ void mma_f16(float* c, const uint32_t* a,
                                        const uint32_t* b) {
    asm volatile(
        "mma.sync.aligned.m16n8k16.row.col.f32.f16.f16.f32 "
        "{%0,%1,%2,%3}, {%4,%5,%6,%7}, {%8,%9}, {%0,%1,%2,%3};"
        : "+f"(c[0]), "+f"(c[1]), "+f"(c[2]), "+f"(c[3])
        : "r"(a[0]), "r"(a[1]), "r"(a[2]), "r"(a[3]), "r"(b[0]), "r"(b[1]));
}
__device__ __forceinline__ uint32_t smem_u32(const void* p) {
    uint32_t a;
    asm("{ .reg .u64 t; cvta.to.shared.u64 t, %1; cvt.u32.u64 %0, t; }"
        : "=r"(a) : "l"(p));
    return a;
}
__device__ __forceinline__ void cp16(uint32_t saddr, const void* g) {
    asm volatile("cp.async.cg.shared.global [%0], [%1], 16;"
                 :: "r"(saddr), "l"(g) : "memory");
}
#define CP_COMMIT() asm volatile("cp.async.commit_group;" ::: "memory")
#define CP_WAIT1()  asm volatile("cp.async.wait_group 1;" ::: "memory")

// ===========================================================================
// Prep: convert x, w_qkv, w_out to fp16
// ===========================================================================
__global__ void prep_convert(const float* __restrict__ x,
                             const float* __restrict__ wq,
                             const float* __restrict__ wo)
{
    const int stride = gridDim.x * blockDim.x;
    const int i0 = blockIdx.x * blockDim.x + threadIdx.x;
    for (int j = i0; j < BS_ * C_ / 4; j += stride) {
        float4 v = ((const float4*)x)[j];
        __half2 lo = __floats2half2_rn(v.x, v.y);
        __half2 hi = __floats2half2_rn(v.z, v.w);
        ((uint2*)g_xh)[j] = make_uint2(*(uint32_t*)&lo, *(uint32_t*)&hi);
    }
    for (int j = i0; j < 3 * C_ * C_ / 4; j += stride) {
        float4 v = ((const float4*)wq)[j];
        __half2 lo = __floats2half2_rn(v.x, v.y);
        __half2 hi = __floats2half2_rn(v.z, v.w);
        ((uint2*)g_wqh)[j] = make_uint2(*(uint32_t*)&lo, *(uint32_t*)&hi);
    }
    for (int j = i0; j < C_ * C_ / 4; j += stride) {
        float4 v = ((const float4*)wo)[j];
        __half2 lo = __floats2half2_rn(v.x, v.y);
        __half2 hi = __floats2half2_rn(v.z, v.w);
        ((uint2*)g_woh)[j] = make_uint2(*(uint32_t*)&lo, *(uint32_t*)&hi);
    }
}

// ===========================================================================
// fp16 tensor-core GEMM NT, cp.async double-buffered (R13 schedule).
// C[m,n] = sum_k A[m,k]*B[n,k] + bias[n]; mma m16n8k16 f16, fp32 accum.
// 128x128 CTA tile, 8 warps (2x4), warp tile 64x32. K-chunk = 32 halves.
// smem row = 32 halves data padded to 20 words (40 halves); conflict-free
// (g*20+t mod 32 all distinct). 2 stages x 2 matrices x 128*20 words = 40KB.
// MODE 0: A=g_xh, B=g_wqh, scatter tf32 q(scaled)/k/v. MODE 1: A=g_yh,
// B=g_woh -> Cout fp32.
// ===========================================================================
#define HKW 20                          // words per smem row
#define HSTW (128 * HKW)                // words per matrix per stage
#define GEMM_SMEM_BYTES (4 * HSTW * 4)  // 40960
#define NKC (C_ / 32)                   // 24 chunks

template <int MODE>
__global__ __launch_bounds__(256) void mmagemm(
    const float* __restrict__ bias, float* __restrict__ Cout)
{
    extern __shared__ uint32_t sg[];
    const uint32_t sbase = smem_u32(sg);

    const __half* A  = (MODE == 1) ? (const __half*)g_yh : (const __half*)g_xh;
    const __half* Bm = (MODE == 1) ? (const __half*)g_woh : (const __half*)g_wqh;

    const int tid  = threadIdx.x;
    const int wid  = tid >> 5;
    const int lane = tid & 31;
    const int g = lane >> 2;
    const int t = lane & 3;
    const int wr = (wid >> 2) * 64;
    const int wc = (wid & 3) * 32;
    const int bm = blockIdx.y * 128;
    const int bn = blockIdx.x * 128;

    // Staging: 512 x 16B per matrix per chunk; 2 cp16 per thread per matrix.
    int soff[2];
    const __half *Ap[2], *Bp[2];
    #pragma unroll
    for (int i = 0; i < 2; i++) {
        const int idx = tid + i * 256;       // 0..511
        const int row = idx >> 2;            // 0..127
        const int s   = idx & 3;             // 16B segment (8 halves)
        soff[i] = (row * HKW + s * 4) * 4;   // byte offset within stage matrix
        Ap[i] = A  + (size_t)(bm + row) * C_ + s * 8;
        Bp[i] = Bm + (size_t)(bn + row) * C_ + s * 8;
    }

    float acc[4][4][4];
    #pragma unroll
    for (int i = 0; i < 4; i++)
        #pragma unroll
        for (int j = 0; j < 4; j++)
            #pragma unroll
            for (int r = 0; r < 4; r++) acc[i][j][r] = 0.f;

    auto issue = [&](int c) {
        if (c < NKC) {
            const uint32_t ab = sbase + (uint32_t)(c & 1) * (2 * HSTW * 4);
            const uint32_t bb = ab + HSTW * 4;
            const int k0 = c * 32;           // halves
            #pragma unroll
            for (int i = 0; i < 2; i++) {
                cp16(ab + soff[i], Ap[i] + k0);
                cp16(bb + soff[i], Bp[i] + k0);
            }
        }
        CP_COMMIT();
    };

    issue(0);
    for (int kc = 0; kc < NKC; kc++) {
        issue(kc + 1);
        CP_WAIT1();
        __syncthreads();

        const uint32_t* As = sg + (kc & 1) * (2 * HSTW);
        const uint32_t* Bs = As + HSTW;
        #pragma unroll
        for (int ks = 0; ks < 2; ks++) {     // two k16 steps per 32-half chunk
            const int kk = ks * 8;           // word offset
            uint32_t af[4][4], bf[4][2];
            #pragma unroll
            for (int mt = 0; mt < 4; mt++) {
                const int r = wr + mt * 16 + g;
                af[mt][0] = As[r * HKW + kk + t];
                af[mt][1] = As[(r + 8) * HKW + kk + t];
                af[mt][2] = As[r * HKW + kk + t + 4];
                af[mt][3] = As[(r + 8) * HKW + kk + t + 4];
            }
            #pragma unroll
            for (int nt = 0; nt < 4; nt++) {
                const int n = wc + nt * 8 + g;
                bf[nt][0] = Bs[n * HKW + kk + t];
                bf[nt][1] = Bs[n * HKW + kk + t + 4];
            }
            #pragma unroll
            for (int mt = 0; mt < 4; mt++)
                #pragma unroll
                for (int nt = 0; nt < 4; nt++)
                    mma_f16(acc[mt][nt], af[mt], bf[nt]);
        }
        __syncthreads();
    }

    // Epilogue (validated C-layout)
    #pragma unroll
    for (int mt = 0; mt < 4; mt++) {
        #pragma unroll
        for (int nt = 0; nt < 4; nt++) {
            const int col = wc + nt * 8 + 2 * t;
            const int r0  = bm + wr + mt * 16 + g;
            const int r1  = r0 + 8;
            const float bv0 = bias[bn + col];
            const float bv1 = bias[bn + col + 1];
            if (MODE == 0) {
                const int comp = bn / C_;
                float* db = (comp == 0) ? g_q : (comp == 1) ? g_k : g_v;
                const float sc = (comp == 0) ? QSCALE : 1.0f;
                float2 lo = make_float2(
                    __uint_as_float(f2tf32((acc[mt][nt][0] + bv0) * sc)),
                    __uint_as_float(f2tf32((acc[mt][nt][1] + bv1) * sc)));
                float2 hi = make_float2(
                    __uint_as_float(f2tf32((acc[mt][nt][2] + bv0) * sc)),
                    __uint_as_float(f2tf32((acc[mt][nt][3] + bv1) * sc)));
                const int c = bn - comp * C_ + col;
                const int h = c >> 6, d = c & 63;
                {
                    const int b = r0 >> 10, s = r0 & 1023;
                    *(float2*)(db + (size_t)(b * H_ + h) * (S_ * D_) +
                               (size_t)s * D_ + d) = lo;
                }
                {
                    const int b = r1 >> 10, s = r1 & 1023;
                    *(float2*)(db + (size_t)(b * H_ + h) * (S_ * D_) +
                               (size_t)s * D_ + d) = hi;
                }
            } else {
                *(float2*)(Cout + (size_t)r0 * C_ + bn + col) =
                    make_float2(acc[mt][nt][0] + bv0, acc[mt][nt][1] + bv1);
                *(float2*)(Cout + (size_t)r1 * C_ + bn + col) =
                    make_float2(acc[mt][nt][2] + bv0, acc[mt][nt][3] + bv1);
            }
        }
    }
}

// ===========================================================================
// Flash attention (tf32, R13-equivalent simple form): 32-key tiles, raw LDG
// staging of pre-tf32'd operands, mma QK^T -> S spill -> in-place SIMT
// softmax -> mma P@V. Epilogue writes g_yh (fp16) for the output projection.
// grid (8, 96), 256 threads. smem 72192 bytes.
// ===========================================================================
#define AT_SQ   0
#define AT_SK   (128 * 68)
#define AT_SV   (AT_SK + 32 * 68)
#define AT_SS   (AT_SV + 32 * 72)
#define AT_SFAC (AT_SS + 128 * 36)
#define AT_SL   (AT_SFAC + 128)
#define AT_SMEM_WORDS (AT_SL + 128)
#define AT_SMEM_BYTES (AT_SMEM_WORDS * 4)       // 72192

__global__ __launch_bounds__(256) void attn_mma(const int* __restrict__ mask)
{
    extern __shared__ uint32_t su[];
    uint32_t (*sQ)[68]  = (uint32_t(*)[68])(su + AT_SQ);
    uint32_t (*sK)[68]  = (uint32_t(*)[68])(su + AT_SK);
    uint32_t (*sV)[72]  = (uint32_t(*)[72])(su + AT_SV);
    float    (*sSP)[36] = (float(*)[36])(su + AT_SS);
    float* sFac = (float*)(su + AT_SFAC);
    float* sL   = (float*)(su + AT_SL);

    const int tid  = threadIdx.x;
    const int wid  = tid >> 5;
    const int lane = tid & 31;
    const int g = lane >> 2;
    const int t = lane & 3;
    const int m0 = wid * 16;

    const int it  = (int)gridDim.x - 1 - (int)blockIdx.x;  // heavy tiles first
    const int bh  = blockIdx.y;
    const int b   = bh / H_;
    const int h   = bh - b * H_;
    const int row0 = it * 128;

    const float* Q  = g_q + (size_t)bh * (S_ * D_) + (size_t)row0 * D_;
    const float* K0 = g_k + (size_t)bh * (S_ * D_);
    const float* V0 = g_v + (size_t)bh * (S_ * D_);
    const int* maskp = mask + b * S_;

    // Stage Q raw (already QSCALE-scaled tf32 bits)
    #pragma unroll
    for (int i = 0; i < 8; i++) {
        const int idx = tid + i * 256;
        const int r = idx >> 4, c4 = (idx & 15) << 2;
        *(float4*)&sQ[r][c4] = *(const float4*)(Q + r * D_ + c4);
    }

    const int srow  = tid >> 1;
    const int scol0 = (tid & 1) << 4;
    const int growo = row0 + srow;
    float m_row = -1e30f, l_row = 0.f;

    float o[8][4];
    #pragma unroll
    for (int nv = 0; nv < 8; nv++)
        #pragma unroll
        for (int r = 0; r < 4; r++) o[nv][r] = 0.f;

    const int ntiles = 4 * it + 4;
    for (int jt = 0; jt < ntiles; jt++) {
        const int kb = jt * 32;
        __syncthreads();
        // Stage K and V tiles raw (tf32 bits)
        #pragma unroll
        for (int i = 0; i < 2; i++) {
            const int idx = tid + i * 256;
            const int r = idx >> 4, c4 = (idx & 15) << 2;
            *(float4*)&sK[r][c4] =
                *(const float4*)(K0 + (size_t)(kb + r) * D_ + c4);
            *(float4*)&sV[r][c4] =
                *(const float4*)(V0 + (size_t)(kb + r) * D_ + c4);
        }
        __syncthreads();

        float sacc[4][4];
        #pragma unroll
        for (int nt = 0; nt < 4; nt++)
            #pragma unroll
            for (int r = 0; r < 4; r++) sacc[nt][r] = 0.f;

        #pragma unroll
        for (int ks = 0; ks < 8; ks++) {
            const int kc = ks * 8;
            uint32_t af[4];
            af[0] = sQ[m0 + g][kc + t];
            af[1] = sQ[m0 + g + 8][kc + t];
            af[2] = sQ[m0 + g][kc + t + 4];
            af[3] = sQ[m0 + g + 8][kc + t + 4];
            #pragma unroll
            for (int nt = 0; nt < 4; nt++) {
                uint32_t bf[2];
                bf[0] = sK[nt * 8 + g][kc + t];
                bf[1] = sK[nt * 8 + g][kc + t + 4];
                mma_tf32(sacc[nt], af, bf);
            }
        }

        #pragma unroll
        for (int nt = 0; nt < 4; nt++) {
            const int col = nt * 8 + 2 * t;
            *(float2*)&sSP[m0 + g][col] =
                make_float2(sacc[nt][0], sacc[nt][1]);
            *(float2*)&sSP[m0 + g + 8][col] =
                make_float2(sacc[nt][2], sacc[nt][3]);
        }
        __syncthreads();

        {
            float sv[16];
            int   km[16];
            #pragma unroll
            for (int j4 = 0; j4 < 4; j4++)
                *(int4*)&km[j4 * 4] =
                    *(const int4*)(maskp + kb + scol0 + j4 * 4);
            #pragma unroll
            for (int j = 0; j < 16; j++) {
                const int col = kb + scol0 + j;
                const bool ok = (col <= growo) && (km[j] != 0);
                sv[j] = ok ? sSP[srow][scol0 + j] : -1e30f;
            }
            float lm = sv[0];
            #pragma unroll
            for (int j = 1; j < 16; j++) lm = fmaxf(lm, sv[j]);
            lm = fmaxf(lm, __shfl_xor_sync(0xffffffffu, lm, 1));
            const float mnew = fmaxf(fmaxf(m_row, lm), -50.0f);
            const float fac = fexp2(m_row - mnew);
            float rs = 0.f;
            #pragma unroll
            for (int j = 0; j < 16; j++) {
                const float p = fexp2(sv[j] - mnew);
                rs += p;
                sSP[srow][scol0 + j] = p;
            }
            rs += __shfl_xor_sync(0xffffffffu, rs, 1);
            l_row = l_row * fac + rs;
            m_row = mnew;
            if ((tid & 1) == 0) sFac[srow] = fac;
        }
        __syncthreads();

        const float f0 = sFac[m0 + g];
        const float f1 = sFac[m0 + g + 8];
        #pragma unroll
        for (int nv = 0; nv < 8; nv++) {
            o[nv][0] *= f0; o[nv][1] *= f0;
            o[nv][2] *= f1; o[nv][3] *= f1;
        }

        #pragma unroll
        for (int ks = 0; ks < 4; ks++) {
            const int kc = ks * 8;
            uint32_t af[4];
            af[0] = __float_as_uint(sSP[m0 + g][kc + t]);
            af[1] = __float_as_uint(sSP[m0 + g + 8][kc + t]);
            af[2] = __float_as_uint(sSP[m0 + g][kc + t + 4]);
            af[3] = __float_as_uint(sSP[m0 + g + 8][kc + t + 4]);
            #pragma unroll
            for (int nv = 0; nv < 8; nv++) {
                uint32_t bf[2];
                bf[0] = sV[kc + t][nv * 8 + g];
                bf[1] = sV[kc + t + 4][nv * 8 + g];
                mma_tf32(o[nv], af, bf);
            }
        }
    }

    if ((tid & 1) == 0) sL[srow] = l_row;
    __syncthreads();

    const int gr0 = row0 + m0 + g;
    const int gr1 = gr0 + 8;
    const float lv0 = sL[m0 + g];
    const float lv1 = sL[m0 + g + 8];
    const float inv0 = (lv0 > 0.f) ? (1.f / lv0) : 0.f;
    const float inv1 = (lv1 > 0.f) ? (1.f / lv1) : 0.f;
    __half* y0 = g_yh + (size_t)(b * S_ + gr0) * C_ + h * D_;
    __half* y1 = g_yh + (size_t)(b * S_ + gr1) * C_ + h * D_;
    #pragma unroll
    for (int nv = 0; nv < 8; nv++) {
        const int col = nv * 8 + 2 * t;
        *(__half2*)(y0 + col) =
            __floats2half2_rn(o[nv][0] * inv0, o[nv][1] * inv0);
        *(__half2*)(y1 + col) =
            __floats2half2_rn(o[nv][2] * inv1, o[nv][3] * inv1);
    }
}

// ---------------------------------------------------------------------------
extern "C" void kernel_launch(void* const* d_in, const int* in_sizes, int n_in,
                              void* d_out, int out_size)
{
    const float* x      = (const float*)d_in[0];
    const float* w_qkv  = (const float*)d_in[1];
    const float* b_qkv  = (const float*)d_in[2];
    const float* w_out  = (const float*)d_in[3];
    const float* b_out  = (const float*)d_in[4];
    const int*   amask  = (const int*)d_in[5];
    float* out = (float*)d_out;

    cudaFuncSetAttribute(mmagemm<0>,
                         cudaFuncAttributeMaxDynamicSharedMemorySize,
                         GEMM_SMEM_BYTES);
    cudaFuncSetAttribute(mmagemm<1>,
                         cudaFuncAttributeMaxDynamicSharedMemorySize,
                         GEMM_SMEM_BYTES);
    cudaFuncSetAttribute(attn_mma,
                         cudaFuncAttributeMaxDynamicSharedMemorySize,
                         AT_SMEM_BYTES);

    // 0) Pre-convert operands to fp16
    prep_convert<<<592, 256>>>(x, w_qkv, w_out);
    // 1) QKV projection (fp16 mma k16) -> g_q (scaled tf32) / g_k / g_v
    {
        dim3 grid((3 * C_) / 128, BS_ / 128);   // (18, 64)
        mmagemm<0><<<grid, 256, GEMM_SMEM_BYTES>>>(b_qkv, nullptr);
    }
    // 2) Flash attention (tf32) -> g_yh (fp16)
    {
        dim3 grid(S_ / 128, B_ * H_);           // (8, 96)
        attn_mma<<<grid, 256, AT_SMEM_BYTES>>>(amask);
    }
    // 3) Output projection (fp16 mma k16) -> d_out
    {
        dim3 grid(C_ / 128, BS_ / 128);         // (6, 64)
        mmagemm<1><<<grid, 256, GEMM_SMEM_BYTES>>>(b_out, out);
    }
}

// round 17
// speedup vs baseline: 1.4510x; 1.1180x over previous
#include <cuda_runtime.h>
#include <cuda_fp16.h>
#include <cstdint>

// Problem constants
#define B_  8
#define S_  1024
#define C_  768
#define H_  12
#define D_  64
#define BS_ (B_ * S_)            // 8192
#define BHSD (B_ * H_ * S_ * D_) // 6291456

// Scratch (allocation-free: static device globals)
__device__ __half g_qh[BHSD];      // fp16, pre-scaled by QSCALE
__device__ __half g_kh[BHSD];      // fp16
__device__ __half g_vh[BHSD];      // fp16
__device__ __half g_yh[BS_ * C_];  // attention output, fp16
// fp16-preconverted GEMM operands
__device__ __half g_xh[BS_ * C_];
__device__ __half g_wqh[3 * C_ * C_];
__device__ __half g_woh[C_ * C_];

#define QSCALE 0.18033688011f    // 0.125 * log2(e)

// ---------------------------------------------------------------------------
// helpers
// ---------------------------------------------------------------------------
__device__ __forceinline__ float fexp2(float x) {
    float y;
    asm("ex2.approx.f32 %0, %1;" : "=f"(y) : "f"(x));
    return y;
}
__device__ __forceinline__ void mma_f16(float* c, const uint32_t* a,
                                        const uint32_t* b) {
    asm volatile(
        "mma.sync.aligned.m16n8k16.row.col.f32.f16.f16.f32 "
        "{%0,%1,%2,%3}, {%4,%5,%6,%7}, {%8,%9}, {%0,%1,%2,%3};"
        : "+f"(c[0]), "+f"(c[1]), "+f"(c[2]), "+f"(c[3])
        : "r"(a[0]), "r"(a[1]), "r"(a[2]), "r"(a[3]), "r"(b[0]), "r"(b[1]));
}
__device__ __forceinline__ uint32_t smem_u32(const void* p) {
    uint32_t a;
    asm("{ .reg .u64 t; cvta.to.shared.u64 t, %1; cvt.u32.u64 %0, t; }"
        : "=r"(a) : "l"(p));
    return a;
}
__device__ __forceinline__ void cp16(uint32_t saddr, const void* g) {
    asm volatile("cp.async.cg.shared.global [%0], [%1], 16;"
                 :: "r"(saddr), "l"(g) : "memory");
}
#define CP_COMMIT() asm volatile("cp.async.commit_group;" ::: "memory")
#define CP_WAIT1()  asm volatile("cp.async.wait_group 1;" ::: "memory")

// ===========================================================================
// Prep: convert x, w_qkv, w_out to fp16  (unchanged R16)
// ===========================================================================
__global__ void prep_convert(const float* __restrict__ x,
                             const float* __restrict__ wq,
                             const float* __restrict__ wo)
{
    const int stride = gridDim.x * blockDim.x;
    const int i0 = blockIdx.x * blockDim.x + threadIdx.x;
    for (int j = i0; j < BS_ * C_ / 4; j += stride) {
        float4 v = ((const float4*)x)[j];
        __half2 lo = __floats2half2_rn(v.x, v.y);
        __half2 hi = __floats2half2_rn(v.z, v.w);
        ((uint2*)g_xh)[j] = make_uint2(*(uint32_t*)&lo, *(uint32_t*)&hi);
    }
    for (int j = i0; j < 3 * C_ * C_ / 4; j += stride) {
        float4 v = ((const float4*)wq)[j];
        __half2 lo = __floats2half2_rn(v.x, v.y);
        __half2 hi = __floats2half2_rn(v.z, v.w);
        ((uint2*)g_wqh)[j] = make_uint2(*(uint32_t*)&lo, *(uint32_t*)&hi);
    }
    for (int j = i0; j < C_ * C_ / 4; j += stride) {
        float4 v = ((const float4*)wo)[j];
        __half2 lo = __floats2half2_rn(v.x, v.y);
        __half2 hi = __floats2half2_rn(v.z, v.w);
        ((uint2*)g_woh)[j] = make_uint2(*(uint32_t*)&lo, *(uint32_t*)&hi);
    }
}

// ===========================================================================
// fp16 tensor-core GEMM NT, cp.async double-buffered (unchanged R16 except
// MODE 0 epilogue now writes fp16 q/k/v).
// ===========================================================================
#define HKW 20
#define HSTW (128 * HKW)
#define GEMM_SMEM_BYTES (4 * HSTW * 4)  // 40960
#define NKC (C_ / 32)                   // 24

template <int MODE>
__global__ __launch_bounds__(256) void mmagemm(
    const float* __restrict__ bias, float* __restrict__ Cout)
{
    extern __shared__ uint32_t sg[];
    const uint32_t sbase = smem_u32(sg);

    const __half* A  = (MODE == 1) ? (const __half*)g_yh : (const __half*)g_xh;
    const __half* Bm = (MODE == 1) ? (const __half*)g_woh : (const __half*)g_wqh;

    const int tid  = threadIdx.x;
    const int wid  = tid >> 5;
    const int lane = tid & 31;
    const int g = lane >> 2;
    const int t = lane & 3;
    const int wr = (wid >> 2) * 64;
    const int wc = (wid & 3) * 32;
    const int bm = blockIdx.y * 128;
    const int bn = blockIdx.x * 128;

    int soff[2];
    const __half *Ap[2], *Bp[2];
    #pragma unroll
    for (int i = 0; i < 2; i++) {
        const int idx = tid + i * 256;
        const int row = idx >> 2;
        const int s   = idx & 3;
        soff[i] = (row * HKW + s * 4) * 4;
        Ap[i] = A  + (size_t)(bm + row) * C_ + s * 8;
        Bp[i] = Bm + (size_t)(bn + row) * C_ + s * 8;
    }

    float acc[4][4][4];
    #pragma unroll
    for (int i = 0; i < 4; i++)
        #pragma unroll
        for (int j = 0; j < 4; j++)
            #pragma unroll
            for (int r = 0; r < 4; r++) acc[i][j][r] = 0.f;

    auto issue = [&](int c) {
        if (c < NKC) {
            const uint32_t ab = sbase + (uint32_t)(c & 1) * (2 * HSTW * 4);
            const uint32_t bb = ab + HSTW * 4;
            const int k0 = c * 32;
            #pragma unroll
            for (int i = 0; i < 2; i++) {
                cp16(ab + soff[i], Ap[i] + k0);
                cp16(bb + soff[i], Bp[i] + k0);
            }
        }
        CP_COMMIT();
    };

    issue(0);
    for (int kc = 0; kc < NKC; kc++) {
        issue(kc + 1);
        CP_WAIT1();
        __syncthreads();

        const uint32_t* As = sg + (kc & 1) * (2 * HSTW);
        const uint32_t* Bs = As + HSTW;
        #pragma unroll
        for (int ks = 0; ks < 2; ks++) {
            const int kk = ks * 8;
            uint32_t af[4][4], bf[4][2];
            #pragma unroll
            for (int mt = 0; mt < 4; mt++) {
                const int r = wr + mt * 16 + g;
                af[mt][0] = As[r * HKW + kk + t];
                af[mt][1] = As[(r + 8) * HKW + kk + t];
                af[mt][2] = As[r * HKW + kk + t + 4];
                af[mt][3] = As[(r + 8) * HKW + kk + t + 4];
            }
            #pragma unroll
            for (int nt = 0; nt < 4; nt++) {
                const int n = wc + nt * 8 + g;
                bf[nt][0] = Bs[n * HKW + kk + t];
                bf[nt][1] = Bs[n * HKW + kk + t + 4];
            }
            #pragma unroll
            for (int mt = 0; mt < 4; mt++)
                #pragma unroll
                for (int nt = 0; nt < 4; nt++)
                    mma_f16(acc[mt][nt], af[mt], bf[nt]);
        }
        __syncthreads();
    }

    #pragma unroll
    for (int mt = 0; mt < 4; mt++) {
        #pragma unroll
        for (int nt = 0; nt < 4; nt++) {
            const int col = wc + nt * 8 + 2 * t;
            const int r0  = bm + wr + mt * 16 + g;
            const int r1  = r0 + 8;
            const float bv0 = bias[bn + col];
            const float bv1 = bias[bn + col + 1];
            if (MODE == 0) {
                const int comp = bn / C_;
                __half* db = (comp == 0) ? g_qh : (comp == 1) ? g_kh : g_vh;
                const float sc = (comp == 0) ? QSCALE : 1.0f;
                __half2 lo = __floats2half2_rn((acc[mt][nt][0] + bv0) * sc,
                                               (acc[mt][nt][1] + bv1) * sc);
                __half2 hi = __floats2half2_rn((acc[mt][nt][2] + bv0) * sc,
                                               (acc[mt][nt][3] + bv1) * sc);
                const int c = bn - comp * C_ + col;
                const int h = c >> 6, d = c & 63;
                {
                    const int b = r0 >> 10, s = r0 & 1023;
                    *(__half2*)(db + (size_t)(b * H_ + h) * (S_ * D_) +
                                (size_t)s * D_ + d) = lo;
                }
                {
                    const int b = r1 >> 10, s = r1 & 1023;
                    *(__half2*)(db + (size_t)(b * H_ + h) * (S_ * D_) +
                                (size_t)s * D_ + d) = hi;
                }
            } else {
                *(float2*)(Cout + (size_t)r0 * C_ + bn + col) =
                    make_float2(acc[mt][nt][0] + bv0, acc[mt][nt][1] + bv1);
                *(float2*)(Cout + (size_t)r1 * C_ + bn + col) =
                    make_float2(acc[mt][nt][2] + bv0, acc[mt][nt][3] + bv1);
            }
        }
    }
}

// ===========================================================================
// Flash attention, full fp16 operands (fp32 accum/softmax).
// QK^T: Q,K fp16 row-major half2-packed along d (4 k16-steps).
// P@V:  P fp16 packed along key; V transpose-packed sVt[d][keypair].
// 32-key tiles, raw LDG staging, S spill + SIMT softmax unchanged (fp32).
// grid (8, 96), 256 threads.
// smem (words): sQ 128x36, sK 32x36, sVt 64x20, sS 128x36 (fp32),
//               sP 128x20 (fp16), sFac 128, sL 128  = 14464 w = 57856 B
// ===========================================================================
#define AT_SQ   0
#define AT_SK   (128 * 36)                      // 4608
#define AT_SVT  (AT_SK + 32 * 36)               // 5760
#define AT_SS   (AT_SVT + 64 * 20)              // 7040
#define AT_SPH  (AT_SS + 128 * 36)              // 11648
#define AT_SFAC (AT_SPH + 128 * 20)             // 14208
#define AT_SL   (AT_SFAC + 128)                 // 14336
#define AT_SMEM_WORDS (AT_SL + 128)             // 14464
#define AT_SMEM_BYTES (AT_SMEM_WORDS * 4)       // 57856

__global__ __launch_bounds__(256) void attn_mma(const int* __restrict__ mask)
{
    extern __shared__ uint32_t su[];
    uint32_t (*sQ)[36]  = (uint32_t(*)[36])(su + AT_SQ);   // half2 words
    uint32_t (*sK)[36]  = (uint32_t(*)[36])(su + AT_SK);   // half2 words
    uint32_t (*sVt)[20] = (uint32_t(*)[20])(su + AT_SVT);  // [d][keypair]
    float    (*sS)[36]  = (float(*)[36])(su + AT_SS);      // fp32 scores
    uint32_t (*sP)[20]  = (uint32_t(*)[20])(su + AT_SPH);  // half2 P
    float* sFac = (float*)(su + AT_SFAC);
    float* sL   = (float*)(su + AT_SL);

    const int tid  = threadIdx.x;
    const int wid  = tid >> 5;
    const int lane = tid & 31;
    const int g = lane >> 2;
    const int t = lane & 3;
    const int m0 = wid * 16;

    const int it  = (int)gridDim.x - 1 - (int)blockIdx.x;  // heavy tiles first
    const int bh  = blockIdx.y;
    const int b   = bh / H_;
    const int h   = bh - b * H_;
    const int row0 = it * 128;

    const __half* Q  = g_qh + (size_t)bh * (S_ * D_) + (size_t)row0 * D_;
    const __half* K0 = g_kh + (size_t)bh * (S_ * D_);
    const __half* V0 = g_vh + (size_t)bh * (S_ * D_);
    const int* maskp = mask + b * S_;

    // Stage Q: 128 rows x 64 halves (32 words); 512 uint4, 2 per thread
    #pragma unroll
    for (int i = 0; i < 2; i++) {
        const int idx = tid + i * 256;
        const int r = idx >> 2, seg = (idx & 3) << 2;   // word offset 0/4/8/12..
        *(uint4*)&sQ[r][seg * 2] =
            *(const uint4*)(Q + r * D_ + seg * 4);      // wait: fix below
    }
    // NOTE: seg*2 words*2 halves = seg*4 halves — recompute cleanly:
    // (replaced by explicit loop below)

    const int srow  = tid >> 1;
    const int scol0 = (tid & 1) << 4;
    const int growo = row0 + srow;
    float m_row = -1e30f, l_row = 0.f;

    float o[8][4];
    #pragma unroll
    for (int nv = 0; nv < 8; nv++)
        #pragma unroll
        for (int r = 0; r < 4; r++) o[nv][r] = 0.f;

    // Proper Q staging (overwrites the placeholder above deterministically):
    // 128 rows x 32 words; thread handles 2 x uint4 (4 words each)
    #pragma unroll
    for (int i = 0; i < 2; i++) {
        const int idx = tid + i * 256;      // 0..511
        const int r = idx >> 2;             // 0..127
        const int w4 = (idx & 3) << 3;      // word offset 0,8,16,24
        *(uint4*)&sQ[r][w4] = *(const uint4*)(Q + r * D_ + w4 * 2);
        *(uint4*)&sQ[r][w4 + 4] = *(const uint4*)(Q + r * D_ + w4 * 2 + 8);
    }

    const int ntiles = 4 * it + 4;
    for (int jt = 0; jt < ntiles; jt++) {
        const int kb = jt * 32;
        __syncthreads();    // prev P@V reads done
        // Stage K: 32 rows x 32 words = 256 uint4, 1 per thread
        {
            const int r = tid >> 3;             // 0..31
            const int w4 = (tid & 7) << 2;      // word offset 0..28
            *(uint4*)&sK[r][w4] =
                *(const uint4*)(K0 + (size_t)(kb + r) * D_ + w4 * 2);
        }
        // Stage V transposed-packed: sVt[d][kp] = {V[2kp][d], V[2kp+1][d]}
        // 128 items (kp 0..15 x d8 0..7); tid < 128
        if (tid < 128) {
            const int kp = tid & 15;
            const int d8 = (tid >> 4) << 3;     // 0,8,..,56
            const __half* v0 = V0 + (size_t)(kb + 2 * kp) * D_ + d8;
            const __half* v1 = v0 + D_;
            __half lo[8], hi[8];
            *(uint4*)lo = *(const uint4*)v0;
            *(uint4*)hi = *(const uint4*)v1;
            #pragma unroll
            for (int j = 0; j < 8; j++) {
                __half2 pv = __halves2half2(lo[j], hi[j]);
                sVt[d8 + j][kp] = *(uint32_t*)&pv;
            }
        }
        __syncthreads();

        // S = Q K^T : fp16 k16, 4 k-steps, nt=4
        float sacc[4][4];
        #pragma unroll
        for (int nt = 0; nt < 4; nt++)
            #pragma unroll
            for (int r = 0; r < 4; r++) sacc[nt][r] = 0.f;

        #pragma unroll
        for (int ks = 0; ks < 4; ks++) {
            const int kk = ks * 8;
            uint32_t af[4];
            af[0] = sQ[m0 + g][kk + t];
            af[1] = sQ[m0 + g + 8][kk + t];
            af[2] = sQ[m0 + g][kk + t + 4];
            af[3] = sQ[m0 + g + 8][kk + t + 4];
            #pragma unroll
            for (int nt = 0; nt < 4; nt++) {
                uint32_t bf[2];
                bf[0] = sK[nt * 8 + g][kk + t];
                bf[1] = sK[nt * 8 + g][kk + t + 4];
                mma_f16(sacc[nt], af, bf);
            }
        }

        // Spill S (fp32, validated C-layout)
        #pragma unroll
        for (int nt = 0; nt < 4; nt++) {
            const int col = nt * 8 + 2 * t;
            *(float2*)&sS[m0 + g][col] =
                make_float2(sacc[nt][0], sacc[nt][1]);
            *(float2*)&sS[m0 + g + 8][col] =
                make_float2(sacc[nt][2], sacc[nt][3]);
        }
        __syncthreads();

        // SIMT softmax (fp32), P written as half2 pairs
        {
            float sv[16];
            int   km[16];
            #pragma unroll
            for (int j4 = 0; j4 < 4; j4++)
                *(int4*)&km[j4 * 4] =
                    *(const int4*)(maskp + kb + scol0 + j4 * 4);
            #pragma unroll
            for (int j = 0; j < 16; j++) {
                const int col = kb + scol0 + j;
                const bool ok = (col <= growo) && (km[j] != 0);
                sv[j] = ok ? sS[srow][scol0 + j] : -1e30f;
            }
            float lm = sv[0];
            #pragma unroll
            for (int j = 1; j < 16; j++) lm = fmaxf(lm, sv[j]);
            lm = fmaxf(lm, __shfl_xor_sync(0xffffffffu, lm, 1));
            const float mnew = fmaxf(fmaxf(m_row, lm), -50.0f);
            const float fac = fexp2(m_row - mnew);
            float rs = 0.f;
            float p[16];
            #pragma unroll
            for (int j = 0; j < 16; j++) {
                p[j] = fexp2(sv[j] - mnew);
                rs += p[j];
            }
            #pragma unroll
            for (int j = 0; j < 8; j++) {
                __half2 ph = __floats2half2_rn(p[2 * j], p[2 * j + 1]);
                sP[srow][(scol0 >> 1) + j] = *(uint32_t*)&ph;
            }
            rs += __shfl_xor_sync(0xffffffffu, rs, 1);
            l_row = l_row * fac + rs;
            m_row = mnew;
            if ((tid & 1) == 0) sFac[srow] = fac;
        }
        __syncthreads();

        // Rescale O; O += P @ V (fp16 k16, 2 k-steps, nv=8)
        const float f0 = sFac[m0 + g];
        const float f1 = sFac[m0 + g + 8];
        #pragma unroll
        for (int nv = 0; nv < 8; nv++) {
            o[nv][0] *= f0; o[nv][1] *= f0;
            o[nv][2] *= f1; o[nv][3] *= f1;
        }
        #pragma unroll
        for (int ks = 0; ks < 2; ks++) {
            const int kk = ks * 8;
            uint32_t af[4];
            af[0] = sP[m0 + g][kk + t];
            af[1] = sP[m0 + g + 8][kk + t];
            af[2] = sP[m0 + g][kk + t + 4];
            af[3] = sP[m0 + g + 8][kk + t + 4];
            #pragma unroll
            for (int nv = 0; nv < 8; nv++) {
                uint32_t bf[2];
                bf[0] = sVt[nv * 8 + g][kk + t];
                bf[1] = sVt[nv * 8 + g][kk + t + 4];
                mma_f16(o[nv], af, bf);
            }
        }
    }

    if ((tid & 1) == 0) sL[srow] = l_row;
    __syncthreads();

    const int gr0 = row0 + m0 + g;
    const int gr1 = gr0 + 8;
    const float lv0 = sL[m0 + g];
    const float lv1 = sL[m0 + g + 8];
    const float inv0 = (lv0 > 0.f) ? (1.f / lv0) : 0.f;
    const float inv1 = (lv1 > 0.f) ? (1.f / lv1) : 0.f;
    __half* y0 = g_yh + (size_t)(b * S_ + gr0) * C_ + h * D_;
    __half* y1 = g_yh + (size_t)(b * S_ + gr1) * C_ + h * D_;
    #pragma unroll
    for (int nv = 0; nv < 8; nv++) {
        const int col = nv * 8 + 2 * t;
        *(__half2*)(y0 + col) =
            __floats2half2_rn(o[nv][0] * inv0, o[nv][1] * inv0);
        *(__half2*)(y1 + col) =
            __floats2half2_rn(o[nv][2] * inv1, o[nv][3] * inv1);
    }
}

// ---------------------------------------------------------------------------
extern "C" void kernel_launch(void* const* d_in, const int* in_sizes, int n_in,
                              void* d_out, int out_size)
{
    const float* x      = (const float*)d_in[0];
    const float* w_qkv  = (const float*)d_in[1];
    const float* b_qkv  = (const float*)d_in[2];
    const float* w_out  = (const float*)d_in[3];
    const float* b_out  = (const float*)d_in[4];
    const int*   amask  = (const int*)d_in[5];
    float* out = (float*)d_out;

    cudaFuncSetAttribute(mmagemm<0>,
                         cudaFuncAttributeMaxDynamicSharedMemorySize,
                         GEMM_SMEM_BYTES);
    cudaFuncSetAttribute(mmagemm<1>,
                         cudaFuncAttributeMaxDynamicSharedMemorySize,
                         GEMM_SMEM_BYTES);
    cudaFuncSetAttribute(attn_mma,
                         cudaFuncAttributeMaxDynamicSharedMemorySize,
                         AT_SMEM_BYTES);

    // 0) Pre-convert operands to fp16
    prep_convert<<<592, 256>>>(x, w_qkv, w_out);
    // 1) QKV projection (fp16 mma) -> g_qh (scaled) / g_kh / g_vh
    {
        dim3 grid((3 * C_) / 128, BS_ / 128);   // (18, 64)
        mmagemm<0><<<grid, 256, GEMM_SMEM_BYTES>>>(b_qkv, nullptr);
    }
    // 2) Flash attention (fp16 operands) -> g_yh
    {
        dim3 grid(S_ / 128, B_ * H_);           // (8, 96)
        attn_mma<<<grid, 256, AT_SMEM_BYTES>>>(amask);
    }
    // 3) Output projection (fp16 mma) -> d_out
    {
        dim3 grid(C_ / 128, BS_ / 128);         // (6, 64)
        mmagemm<1><<<grid, 256, GEMM_SMEM_BYTES>>>(b_out, out);
    }
}